// round 4
// baseline (speedup 1.0000x reference)
#include <cuda_runtime.h>
#include <cuda_bf16.h>
#include <cstdint>
#include <math.h>

#define ROWS 8192
#define COLS 256
#define BM 128
#define BN 128
#define BK 32
#define KITERS (COLS / BK)        /* 8 */
#define STAGES 3
#define TILES 64                  /* 8192/128 */
#define NTRI (TILES * (TILES + 1) / 2)  /* 2080 */
#define NFULL (TILES * TILES)           /* 4096 */
#define NBLK (2 * NTRI + NFULL)         /* 8256 */
#define RARE_THRESH 32.0f

// ---------------------------------------------------------------------------
// device scratch
// ---------------------------------------------------------------------------
__device__ __align__(16) __nv_bfloat16 g_Nbf[ROWS * COLS];
__device__ __align__(16) __nv_bfloat16 g_Rbf[ROWS * COLS];
__device__ float g_x2N[ROWS];
__device__ float g_x2R[ROWS];
__device__ float g_part[NBLK];

// ---------------------------------------------------------------------------
// PTX helpers (base-arch only: cp.async, ldmatrix, mma.sync)
// ---------------------------------------------------------------------------
__device__ __forceinline__ uint32_t smem_u32(const void* p) {
    uint32_t a;
    asm("{ .reg .u64 t; cvta.to.shared.u64 t, %1; cvt.u32.u64 %0, t; }" : "=r"(a) : "l"(p));
    return a;
}
#define CP16(dst, src) \
    asm volatile("cp.async.cg.shared.global [%0], [%1], 16;" :: "r"(dst), "l"(src) : "memory")
#define CP_COMMIT() asm volatile("cp.async.commit_group;" ::: "memory")
#define LDSM4(r, addr) \
    asm volatile("ldmatrix.sync.aligned.m8n8.x4.shared.b16 {%0,%1,%2,%3}, [%4];" \
        : "=r"((r)[0]), "=r"((r)[1]), "=r"((r)[2]), "=r"((r)[3]) : "r"(addr))
#define LDSM2(r, addr) \
    asm volatile("ldmatrix.sync.aligned.m8n8.x2.shared.b16 {%0,%1}, [%2];" \
        : "=r"((r)[0]), "=r"((r)[1]) : "r"(addr))
#define MMA16816(d, a, b) \
    asm volatile("mma.sync.aligned.m16n8k16.row.col.f32.bf16.bf16.f32 " \
        "{%0,%1,%2,%3}, {%4,%5,%6,%7}, {%8,%9}, {%0,%1,%2,%3};" \
        : "+f"((d)[0]), "+f"((d)[1]), "+f"((d)[2]), "+f"((d)[3]) \
        : "r"((a)[0]), "r"((a)[1]), "r"((a)[2]), "r"((a)[3]), "r"((b)[0]), "r"((b)[1]))

// ---------------------------------------------------------------------------
// Prep: fp32 -> bf16 row-major + exact fp32 row squared-norms.
// ---------------------------------------------------------------------------
__global__ void prep_kernel(const float* __restrict__ Nf, const float* __restrict__ Rf) {
    const float* src = blockIdx.y ? Rf : Nf;
    __nv_bfloat16* dst = blockIdx.y ? g_Rbf : g_Nbf;
    float* x2 = blockIdx.y ? g_x2R : g_x2N;

    int row = blockIdx.x * 8 + (threadIdx.x >> 5);
    int lane = threadIdx.x & 31;
    const float* p = src + (size_t)row * COLS + lane * 8;
    float4 v0 = *(const float4*)p;
    float4 v1 = *(const float4*)(p + 4);
    float s = 0.f;
    s = fmaf(v0.x, v0.x, s); s = fmaf(v0.y, v0.y, s);
    s = fmaf(v0.z, v0.z, s); s = fmaf(v0.w, v0.w, s);
    s = fmaf(v1.x, v1.x, s); s = fmaf(v1.y, v1.y, s);
    s = fmaf(v1.z, v1.z, s); s = fmaf(v1.w, v1.w, s);

    __align__(16) __nv_bfloat16 b[8];
    b[0] = __float2bfloat16(v0.x); b[1] = __float2bfloat16(v0.y);
    b[2] = __float2bfloat16(v0.z); b[3] = __float2bfloat16(v0.w);
    b[4] = __float2bfloat16(v1.x); b[5] = __float2bfloat16(v1.y);
    b[6] = __float2bfloat16(v1.z); b[7] = __float2bfloat16(v1.w);
    *(uint4*)(dst + (size_t)row * COLS + lane * 8) = *(const uint4*)b;

#pragma unroll
    for (int o = 16; o > 0; o >>= 1) s += __shfl_xor_sync(0xffffffffu, s, o);
    if (lane == 0) x2[row] = s;
}

// ---------------------------------------------------------------------------
// Fused bf16 HMMA Gram + screen + rare-path exact epilogue.
// Flattened active-only grid: [0,2080) NN-upper, [2080,4160) RR-upper,
// [4160,8256) NR full. 3-stage cp.async pipeline, one barrier per k-iter.
// ---------------------------------------------------------------------------
__global__ __launch_bounds__(256, 2)
void mmd_mma_kernel(const float* __restrict__ Nf, const float* __restrict__ Rf) {
    const int bid = blockIdx.x;

    int pass, ti, tj;
    if (bid < 2 * NTRI) {
        pass = bid < NTRI ? 0 : 1;
        int idx = bid - pass * NTRI;
        int r = 0;
        while (idx >= TILES - r) { idx -= TILES - r; r++; }
        ti = r; tj = r + idx;
    } else {
        pass = 2;
        int q = bid - 2 * NTRI;
        ti = q >> 6; tj = q & 63;
    }
    const bool sym = (pass < 2);

    const __nv_bfloat16 *Abf, *Bbf;
    const float *x2a, *x2b, *Af, *Bf;
    if (pass == 0)      { Abf = g_Nbf; Bbf = g_Nbf; x2a = g_x2N; x2b = g_x2N; Af = Nf; Bf = Nf; }
    else if (pass == 1) { Abf = g_Rbf; Bbf = g_Rbf; x2a = g_x2R; x2b = g_x2R; Af = Rf; Bf = Rf; }
    else                { Abf = g_Nbf; Bbf = g_Rbf; x2a = g_x2N; x2b = g_x2R; Af = Nf; Bf = Rf; }

    __shared__ __nv_bfloat16 As[STAGES][BM * BK];
    __shared__ __nv_bfloat16 Bs[STAGES][BN * BK];
    __shared__ float wsum[8];

    const int tid = threadIdx.x, wid = tid >> 5, lane = tid & 31;
    const uint32_t aS = smem_u32(As), bS = smem_u32(Bs);

    const int lrow = tid >> 2;      // 0..63
    const int lchunk = tid & 3;
    const __nv_bfloat16* Ag = Abf + (size_t)(ti * BM) * COLS + lchunk * 8;
    const __nv_bfloat16* Bg = Bbf + (size_t)(tj * BN) * COLS + lchunk * 8;

    // swizzled 16B-chunk offset: row*64B, chunk ^ ((row>>1)&3)
#define SWOFF(buf, row, chunk) \
    ((uint32_t)((((buf) * BM + (row)) * 4 + ((chunk) ^ (((row) >> 1) & 3))) * 16))

#define ISSUE_LOAD(kit, buf) do {                                            \
    int _kb = (kit) * BK;                                                    \
    int _r0 = lrow, _r1 = lrow + 64;                                         \
    CP16(aS + SWOFF(buf, _r0, lchunk), Ag + (size_t)_r0 * COLS + _kb);       \
    CP16(aS + SWOFF(buf, _r1, lchunk), Ag + (size_t)_r1 * COLS + _kb);       \
    CP16(bS + SWOFF(buf, _r0, lchunk), Bg + (size_t)_r0 * COLS + _kb);       \
    CP16(bS + SWOFF(buf, _r1, lchunk), Bg + (size_t)_r1 * COLS + _kb);       \
    CP_COMMIT();                                                             \
} while (0)

    float acc[4][4][4];
#pragma unroll
    for (int mi = 0; mi < 4; mi++)
#pragma unroll
        for (int ni = 0; ni < 4; ni++)
#pragma unroll
            for (int r = 0; r < 4; r++) acc[mi][ni][r] = 0.f;

    const int wm = (wid & 1) * 64;
    const int wn = (wid >> 1) * 32;
    const int a_r = lane & 15, a_c = lane >> 4;
    const int b_r = lane & 7,  b_c = (lane >> 3) & 1;

    // prologue: stages 0,1 in flight
    ISSUE_LOAD(0, 0);
    ISSUE_LOAD(1, 1);

#pragma unroll 1
    for (int it = 0; it < KITERS; it++) {
        if (it == KITERS - 1) asm volatile("cp.async.wait_group 0;" ::: "memory");
        else                  asm volatile("cp.async.wait_group 1;" ::: "memory");
        __syncthreads();

        const int buf = it % STAGES;
        // issue next-next stage into the buffer freed by compute(it-1)
        if (it + 2 < KITERS) ISSUE_LOAD(it + 2, (it + 2) % STAGES);

#pragma unroll
        for (int s = 0; s < 2; s++) {
            uint32_t a_frag[4][4], b_frag[4][2];
#pragma unroll
            for (int mi = 0; mi < 4; mi++)
                LDSM4(a_frag[mi], aS + SWOFF(buf, wm + mi * 16 + a_r, 2 * s + a_c));
#pragma unroll
            for (int ni = 0; ni < 4; ni++)
                LDSM2(b_frag[ni], bS + SWOFF(buf, wn + ni * 8 + b_r, 2 * s + b_c));
#pragma unroll
            for (int mi = 0; mi < 4; mi++)
#pragma unroll
                for (int ni = 0; ni < 4; ni++)
                    MMA16816(acc[mi][ni], a_frag[mi], b_frag[ni]);
        }
    }

    // ---- epilogue: screen d2, exact recompute of rare elements ----
    const int qr = lane >> 2, qc = (lane & 3) * 2;
    float x2i[8], x2j[8];
#pragma unroll
    for (int mi = 0; mi < 4; mi++) {
        x2i[mi * 2 + 0] = x2a[ti * BM + wm + mi * 16 + qr];
        x2i[mi * 2 + 1] = x2a[ti * BM + wm + mi * 16 + qr + 8];
    }
#pragma unroll
    for (int ni = 0; ni < 4; ni++) {
        x2j[ni * 2 + 0] = x2b[tj * BN + wn + ni * 8 + qc];
        x2j[ni * 2 + 1] = x2b[tj * BN + wn + ni * 8 + qc + 1];
    }

    const bool diag = sym && (ti == tj);
    const float base_w = sym ? 2.f : 1.f;
    float ssum = 0.f;
#pragma unroll
    for (int mi = 0; mi < 4; mi++) {
#pragma unroll
        for (int ni = 0; ni < 4; ni++) {
#pragma unroll
            for (int r = 0; r < 4; r++) {
                float x2s = x2i[mi * 2 + (r >> 1)] + x2j[ni * 2 + (r & 1)];
                float d2 = fmaf(-2.f, acc[mi][ni][r], x2s);
                if (d2 < RARE_THRESH) {
                    int i = ti * BM + wm + mi * 16 + qr + (r >> 1) * 8;
                    int j = tj * BN + wn + ni * 8 + qc + (r & 1);
                    const float* ar = Af + (size_t)i * COLS;
                    const float* br = Bf + (size_t)j * COLS;
                    float pd = 0.f;
                    for (int k = 0; k < COLS; k += 4) {
                        float4 av = *(const float4*)(ar + k);
                        float4 bv = *(const float4*)(br + k);
                        pd = fmaf(av.x, bv.x, pd); pd = fmaf(av.y, bv.y, pd);
                        pd = fmaf(av.z, bv.z, pd); pd = fmaf(av.w, bv.w, pd);
                    }
                    float d2p = fmaxf(fmaf(-2.f, pd, x2s), 0.f);
                    float w = base_w;
                    if (diag) w = (j > i) ? 2.f : ((j == i) ? 1.f : 0.f);
                    ssum += w * __expf(-d2p);
                }
            }
        }
    }

    // deterministic block reduction
#pragma unroll
    for (int o = 16; o > 0; o >>= 1) ssum += __shfl_xor_sync(0xffffffffu, ssum, o);
    if (lane == 0) wsum[wid] = ssum;
    __syncthreads();
    if (tid == 0) {
        float t = 0.f;
#pragma unroll
        for (int w = 0; w < 8; w++) t += wsum[w];
        g_part[bid] = t;
    }
#undef ISSUE_LOAD
#undef SWOFF
}

// ---------------------------------------------------------------------------
// Final deterministic reduction + sqrt.
// Slot ranges: [0,2080) NN, [2080,4160) RR, [4160,8256) NR.
// ---------------------------------------------------------------------------
__global__ void finalize_kernel(float* __restrict__ out) {
    __shared__ float sh[256];
    const int tid = threadIdx.x;
    const int lo[3] = {0, NTRI, 2 * NTRI};
    const int hi[3] = {NTRI, 2 * NTRI, NBLK};
    float sums[3];
#pragma unroll
    for (int p = 0; p < 3; p++) {
        float s = 0.f;
        for (int idx = lo[p] + tid; idx < hi[p]; idx += 256) s += g_part[idx];
        sh[tid] = s;
        __syncthreads();
        for (int o = 128; o > 0; o >>= 1) {
            if (tid < o) sh[tid] += sh[tid + o];
            __syncthreads();
        }
        sums[p] = sh[0];
        __syncthreads();
    }
    if (tid == 0) {
        double inv = 1.0 / ((double)ROWS * (double)ROWS);
        double mmd = ((double)sums[0] + (double)sums[1] - 2.0 * (double)sums[2]) * inv;
        if (mmd < 0.0) mmd = 0.0;
        out[0] = (float)sqrt(mmd);
    }
}

// ---------------------------------------------------------------------------
extern "C" void kernel_launch(void* const* d_in, const int* in_sizes, int n_in,
                              void* d_out, int out_size) {
    const float* Nf = (const float*)d_in[0];
    const float* Rf = (const float*)d_in[1];
    float* out = (float*)d_out;
    (void)in_sizes; (void)n_in; (void)out_size;

    dim3 pgrid(ROWS / 8, 2, 1);
    prep_kernel<<<pgrid, 256>>>(Nf, Rf);

    mmd_mma_kernel<<<NBLK, 256>>>(Nf, Rf);

    finalize_kernel<<<1, 256>>>(out);
}